// round 17
// baseline (speedup 1.0000x reference)
#include <cuda_runtime.h>
#include <math.h>

typedef unsigned long long u64;

// ---------------------------------------------------------------------------
// Packed f32x2 helpers (Blackwell FFMA2 — only reachable via PTX fma.rn.f32x2)
// ---------------------------------------------------------------------------
__device__ __forceinline__ u64 pack2(float x) {
    u64 r; asm("mov.b64 %0, {%1, %1};" : "=l"(r) : "f"(x)); return r;
}
__device__ __forceinline__ void unpack2(u64 v, float& lo, float& hi) {
    asm("mov.b64 {%0, %1}, %2;" : "=f"(lo), "=f"(hi) : "l"(v));
}
__device__ __forceinline__ u64 fma2(u64 a, u64 b, u64 c) {
    u64 d; asm("fma.rn.f32x2 %0, %1, %2, %3;" : "=l"(d) : "l"(a), "l"(b), "l"(c));
    return d;
}

// ---------------------------------------------------------------------------
// Problem constants
// ---------------------------------------------------------------------------
#define IMG_H 1280
#define IMG_W 720
#define NH 64
#define NW 36
#define L_BLOCKS 2304
#define OUT_H 5120
#define OUT_W 2880
#define OUT_PLANE (OUT_H * OUT_W)
#define OUT_IMG (3 * OUT_PLANE)

#define G1_C 16
#define G1_H 640
#define G1_W 360
#define G1_AREA (G1_H * G1_W)

// gate1 tiling: pooled 8 rows x 6 cols per CTA
#define G1_TH 8
#define G1_TW 6
#define G1_GY (G1_H / G1_TH)      // 80
#define G1_GX (G1_W / G1_TW)      // 60
#define G1_BLOCKS (G1_GY * G1_GX) // 4800

// gate23 tiling: CTA = 1x2 gate3 outputs -> 64 * 18 = 1152 CTAs
#define G23_BLOCKS (NH * (NW / 2))

#define LIGHT_BASE  G1_BLOCKS                       // 4800
#define G23_BASE    (G1_BLOCKS + L_BLOCKS)          // 7104
#define TOTAL_BLOCKS (G23_BASE + G23_BLOCKS)        // 8256

__device__ float g_g1[G1_C * G1_AREA];
__device__ unsigned g_g1_done;     // completion counter, memset to 0 per launch

// ---------------------------------------------------------------------------
// Fused smem: one path active per block -> union.
// ---------------------------------------------------------------------------
struct SmemLight {
    u64  in2[3][22][36];           // 19008 B
    float wT[27][48];              //  5184 B
    float b[48];
};
struct SmemGate1 {
    u64  in2[3][18][15];
    float wT[27][16];
    float b[16];
};
struct SmemG23 {
    float g1[16][12][23];          // 17664 B (12-row x 22-col halo, pad 23)
    float wT[144][8];              //  4608 B
    float g2[8][5][11];            //  1760 B
    float w3[200];
    float b2[8];
};
union SmemFused {
    SmemLight l;
    SmemGate1 g;
    SmemG23   t;
};

// ---------------------------------------------------------------------------
// ONE kernel, three block ranges:
//   [0, 4800)        gate1: conv1 + maxpool + tanh -> g_g1, then signal
//   [4800, 7104)     light expert (R12 math)
//   [7104, 8256)     gate23: spin-wait on g_g1, conv2+pool+bias -> smem,
//                    gate3 5x5 conv + sigmoid -> class vector
// Dispatch order guarantees gate1 CTAs all launch before any gate23 CTA
// spins -> forward progress -> no deadlock.
// ---------------------------------------------------------------------------
__global__ __launch_bounds__(96)
void fused_kernel(const float* __restrict__ in,
                  const float* __restrict__ wl,
                  const float* __restrict__ bl,
                  const float* __restrict__ w1,
                  const float* __restrict__ b1,
                  const float* __restrict__ w2,
                  const float* __restrict__ b2,
                  const float* __restrict__ w3,
                  const float* __restrict__ b3,
                  float* __restrict__ out)
{
    __shared__ __align__(16) SmemFused sm;
    const int tid = threadIdx.x;

    if (blockIdx.x < LIGHT_BASE) {
        // ================= GATE1 PATH =================
        const int gblk = blockIdx.x;
        const int ty0 = (gblk / G1_GX) * G1_TH;
        const int tx0 = (gblk % G1_GX) * G1_TW;

        for (int i = tid; i < 27 * 16; i += 96) {
            int k = i >> 4, oc = i & 15;
            sm.g.wT[k][oc] = w1[oc * 27 + k];
        }
        if (tid < 16) sm.g.b[tid] = b1[tid];

        for (int i = tid; i < 3 * 18 * 14; i += 96) {
            int x = i % 14;
            int y = (i / 14) % 18;
            int c = i / 252;
            int gy = min(max(ty0 * 2 - 1 + y, 0), IMG_H - 1);
            int gx = min(max(tx0 * 2 - 1 + x, 0), IMG_W - 1);
            sm.g.in2[c][y][x] = pack2(in[c * (IMG_H * IMG_W) + gy * IMG_W + gx]);
        }
        __syncthreads();

        const int half = tid / 48;
        const int pix  = tid - half * 48;
        const int px   = pix % G1_TW;
        const int py   = pix / G1_TW;
        const int oc0  = half * 8;

        u64 acc[2][2][4];
        {
            #pragma unroll
            for (int m = 0; m < 4; m++) {
                u64 b = *(const u64*)&sm.g.b[oc0 + 2 * m];
                acc[0][0][m] = b; acc[0][1][m] = b;
                acc[1][0][m] = b; acc[1][1][m] = b;
            }
        }

        #pragma unroll
        for (int ic = 0; ic < 3; ic++) {
            #pragma unroll
            for (int kh = 0; kh < 3; kh++) {
                u64 xx[2][4];
                #pragma unroll
                for (int dy = 0; dy < 2; dy++)
                    #pragma unroll
                    for (int c = 0; c < 4; c++)
                        xx[dy][c] = sm.g.in2[ic][2 * py + kh + dy][2 * px + c];
                #pragma unroll
                for (int kw = 0; kw < 3; kw++) {
                    const float* wp = &sm.g.wT[ic * 9 + kh * 3 + kw][oc0];
                    ulonglong2 wA = *(const ulonglong2*)(wp);
                    ulonglong2 wB = *(const ulonglong2*)(wp + 4);
                    #pragma unroll
                    for (int dy = 0; dy < 2; dy++)
                        #pragma unroll
                        for (int dx = 0; dx < 2; dx++) {
                            u64 x = xx[dy][dx + kw];
                            acc[dy][dx][0] = fma2(x, wA.x, acc[dy][dx][0]);
                            acc[dy][dx][1] = fma2(x, wA.y, acc[dy][dx][1]);
                            acc[dy][dx][2] = fma2(x, wB.x, acc[dy][dx][2]);
                            acc[dy][dx][3] = fma2(x, wB.y, acc[dy][dx][3]);
                        }
                }
            }
        }

        const int py_g = ty0 + py;
        const int px_g = tx0 + px;
        #pragma unroll
        for (int m = 0; m < 4; m++) {
            float m0 = -1e30f, m1 = -1e30f;
            #pragma unroll
            for (int dy = 0; dy < 2; dy++)
                #pragma unroll
                for (int dx = 0; dx < 2; dx++) {
                    float lo, hi;
                    unpack2(acc[dy][dx][m], lo, hi);
                    m0 = fmaxf(m0, lo);
                    m1 = fmaxf(m1, hi);
                }
            g_g1[(oc0 + 2 * m + 0) * G1_AREA + py_g * G1_W + px_g] = tanhf(m0);
            g_g1[(oc0 + 2 * m + 1) * G1_AREA + py_g * G1_W + px_g] = tanhf(m1);
        }

        // Signal completion (all stores fenced before the count bump)
        __threadfence();
        __syncthreads();
        if (tid == 0) atomicAdd(&g_g1_done, 1u);

    } else if (blockIdx.x < G23_BASE) {
        // ================= LIGHT PATH (R12 math, best known) =================
        const int blk = blockIdx.x - LIGHT_BASE;
        const int bh = blk / NW;
        const int bw = blk % NW;

        for (int i = tid; i < 27 * 48; i += 96) {
            int k = i / 48, oc = i % 48;
            sm.l.wT[k][oc] = wl[oc * 27 + k];
        }
        if (tid < 48) sm.l.b[tid] = bl[tid];

        for (int i = tid; i < 3 * 22 * 22; i += 96) {
            int x = i % 22;
            int y = (i / 22) % 22;
            int c = i / 484;
            float v = 0.0f;
            if (y >= 1 && y <= 20 && x >= 1 && x <= 20)
                v = in[c * (IMG_H * IMG_W) + (bh * 20 + y - 1) * IMG_W + (bw * 20 + x - 1)];
            sm.l.in2[c][y][x] = pack2(v);
        }
        __syncthreads();

        #pragma unroll 1
        for (int it = 0; it < 5; it++) {
            const int item = tid + 96 * it;
            const int cg  = item / 80;
            const int rem = item % 80;
            const int p   = rem >> 2;
            const int q0  = (rem & 3) * 5;
            const int oc0 = cg * 8;
            const int c_img = oc0 >> 4;
            const int r1a = (oc0 & 15) >> 2;

            u64 acc[5][4];
            {
                u64 b0 = *(const u64*)&sm.l.b[oc0 + 0];
                u64 b1v = *(const u64*)&sm.l.b[oc0 + 2];
                u64 b2v = *(const u64*)&sm.l.b[oc0 + 4];
                u64 b3v = *(const u64*)&sm.l.b[oc0 + 6];
                #pragma unroll
                for (int j = 0; j < 5; j++) {
                    acc[j][0] = b0; acc[j][1] = b1v;
                    acc[j][2] = b2v; acc[j][3] = b3v;
                }
            }

            #pragma unroll
            for (int ic = 0; ic < 3; ic++) {
                #pragma unroll
                for (int kh = 0; kh < 3; kh++) {
                    u64 xx[7];
                    #pragma unroll
                    for (int c = 0; c < 7; c++)
                        xx[c] = sm.l.in2[ic][p + kh][q0 + c];
                    #pragma unroll
                    for (int kw = 0; kw < 3; kw++) {
                        const float* wp = &sm.l.wT[ic * 9 + kh * 3 + kw][oc0];
                        ulonglong2 wA = *(const ulonglong2*)(wp);
                        ulonglong2 wB = *(const ulonglong2*)(wp + 4);
                        #pragma unroll
                        for (int j = 0; j < 5; j++) {
                            u64 x = xx[j + kw];
                            acc[j][0] = fma2(x, wA.x, acc[j][0]);
                            acc[j][1] = fma2(x, wA.y, acc[j][1]);
                            acc[j][2] = fma2(x, wB.x, acc[j][2]);
                            acc[j][3] = fma2(x, wB.y, acc[j][3]);
                        }
                    }
                }
            }

            #pragma unroll
            for (int j = 0; j < 5; j++) {
                int q = q0 + j;
                size_t base = (size_t)c_img * OUT_PLANE
                            + (size_t)(bh * 80 + p * 4 + r1a) * OUT_W
                            + (bw * 80 + q * 4);
                float4 v;
                unpack2(acc[j][0], v.x, v.y);
                unpack2(acc[j][1], v.z, v.w);
                v.x = fminf(fmaxf(v.x, 0.0f), 0.6f) + 0.4f;
                v.y = fminf(fmaxf(v.y, 0.0f), 0.6f) + 0.4f;
                v.z = fminf(fmaxf(v.z, 0.0f), 0.6f) + 0.4f;
                v.w = fminf(fmaxf(v.w, 0.0f), 0.6f) + 0.4f;
                *reinterpret_cast<float4*>(&out[base]) = v;

                unpack2(acc[j][2], v.x, v.y);
                unpack2(acc[j][3], v.z, v.w);
                v.x = fminf(fmaxf(v.x, 0.0f), 0.6f) + 0.4f;
                v.y = fminf(fmaxf(v.y, 0.0f), 0.6f) + 0.4f;
                v.z = fminf(fmaxf(v.z, 0.0f), 0.6f) + 0.4f;
                v.w = fminf(fmaxf(v.w, 0.0f), 0.6f) + 0.4f;
                *reinterpret_cast<float4*>(&out[base + OUT_W]) = v;
            }
        }

    } else {
        // ================= GATE23 PATH =================
        const int gidx = blockIdx.x - G23_BASE;    // 0..1151
        const int by   = gidx / (NW / 2);          // gate3 output row 0..63
        const int bx0  = (gidx % (NW / 2)) * 2;    // gate3 output cols bx0, bx0+1
        float* out_cv  = out + OUT_IMG;

        // Weights first (independent of g1)
        for (int i = tid; i < 144 * 8; i += 96) {
            int k = i >> 3, oc = i & 7;
            sm.t.wT[k][oc] = w2[oc * 144 + k];
        }
        for (int i = tid; i < 200; i += 96) sm.t.w3[i] = w3[i];
        if (tid < 8) sm.t.b2[tid] = b2[tid];

        // Wait for ALL gate1 blocks (dispatch order guarantees their progress)
        if (tid == 0) {
            while (atomicAdd(&g_g1_done, 0u) < (unsigned)G1_BLOCKS)
                __nanosleep(200);
        }
        __syncthreads();
        __threadfence();

        // g1 halo: rows [by*10-1, +12), cols [bx0*10-1, +22), edge-clamped
        for (int i = tid; i < 16 * 12 * 22; i += 96) {
            int x = i % 22;
            int y = (i / 22) % 12;
            int c = i / 264;
            int gy = min(max(by * 10 - 1 + y, 0), G1_H - 1);
            int gx = min(max(bx0 * 10 - 1 + x, 0), G1_W - 1);
            sm.t.g1[c][y][x] = g_g1[c * G1_AREA + gy * G1_W + gx];
        }
        __syncthreads();

        // Phase 1: conv2 + maxpool + bias. 50 threads = pooled pixel, 8 ch each.
        if (tid < 50) {
            const int pp = tid / 10;           // 0..4 (g2 row)
            const int qq = tid % 10;           // 0..9 (g2 col)

            u64 acc[2][2][4];
            u64 z = pack2(0.0f);
            #pragma unroll
            for (int dy = 0; dy < 2; dy++)
                #pragma unroll
                for (int dx = 0; dx < 2; dx++)
                    #pragma unroll
                    for (int m = 0; m < 4; m++) acc[dy][dx][m] = z;

            #pragma unroll 1
            for (int ic = 0; ic < 16; ic++) {
                #pragma unroll
                for (int kh = 0; kh < 3; kh++) {
                    u64 xx[2][4];
                    #pragma unroll
                    for (int dy = 0; dy < 2; dy++)
                        #pragma unroll
                        for (int c = 0; c < 4; c++)
                            xx[dy][c] = pack2(sm.t.g1[ic][2 * pp + kh + dy][2 * qq + c]);
                    #pragma unroll
                    for (int kw = 0; kw < 3; kw++) {
                        const float* wp = &sm.t.wT[ic * 9 + kh * 3 + kw][0];
                        ulonglong2 wA = *(const ulonglong2*)(wp);
                        ulonglong2 wB = *(const ulonglong2*)(wp + 4);
                        #pragma unroll
                        for (int dy = 0; dy < 2; dy++)
                            #pragma unroll
                            for (int dx = 0; dx < 2; dx++) {
                                u64 x = xx[dy][dx + kw];
                                acc[dy][dx][0] = fma2(x, wA.x, acc[dy][dx][0]);
                                acc[dy][dx][1] = fma2(x, wA.y, acc[dy][dx][1]);
                                acc[dy][dx][2] = fma2(x, wB.x, acc[dy][dx][2]);
                                acc[dy][dx][3] = fma2(x, wB.y, acc[dy][dx][3]);
                            }
                    }
                }
            }

            #pragma unroll
            for (int m = 0; m < 4; m++) {
                float m0 = -1e30f, m1 = -1e30f;
                #pragma unroll
                for (int dy = 0; dy < 2; dy++)
                    #pragma unroll
                    for (int dx = 0; dx < 2; dx++) {
                        float lo, hi;
                        unpack2(acc[dy][dx][m], lo, hi);
                        m0 = fmaxf(m0, lo);
                        m1 = fmaxf(m1, hi);
                    }
                sm.t.g2[2 * m + 0][pp][qq] = m0 + sm.t.b2[2 * m + 0];
                sm.t.g2[2 * m + 1][pp][qq] = m1 + sm.t.b2[2 * m + 1];
            }
        }
        __syncthreads();

        // Phase 2: gate3. Warp w (0/1) -> output (by, bx0 + w).
        const int warp = tid >> 5;
        const int lane = tid & 31;
        if (warp < 2) {
            float v = 0.0f;
            if (lane < 25) {
                int ky = lane / 5, kx = lane % 5;
                #pragma unroll
                for (int ic = 0; ic < 8; ic++)
                    v = fmaf(sm.t.g2[ic][ky][warp * 5 + kx], sm.t.w3[ic * 25 + lane], v);
            }
            v += __shfl_xor_sync(0xffffffffu, v, 16);
            v += __shfl_xor_sync(0xffffffffu, v, 8);
            v += __shfl_xor_sync(0xffffffffu, v, 4);
            v += __shfl_xor_sync(0xffffffffu, v, 2);
            v += __shfl_xor_sync(0xffffffffu, v, 1);

            if (lane == 0)
                out_cv[by * NW + (bx0 + warp)] = 1.0f / (1.0f + expf(-(v + b3[0])));
        }
    }
}

// ---------------------------------------------------------------------------
// Launch: counter reset (memset node) + ONE kernel.
// ---------------------------------------------------------------------------
extern "C" void kernel_launch(void* const* d_in, const int* in_sizes, int n_in,
                              void* d_out, int out_size)
{
    const float* in = (const float*)d_in[0];
    const float* w1 = (const float*)d_in[1];
    const float* b1 = (const float*)d_in[2];
    const float* w2 = (const float*)d_in[3];
    const float* b2 = (const float*)d_in[4];
    const float* w3 = (const float*)d_in[5];
    const float* b3 = (const float*)d_in[6];
    const float* wl = (const float*)d_in[7];
    const float* bl = (const float*)d_in[8];
    // complex expert weights (d_in[9..14]) are provably dead: sigmoid(x) > 1 never

    float* out = (float*)d_out;

    static void* s_ctr = nullptr;
    if (!s_ctr) cudaGetSymbolAddress(&s_ctr, g_g1_done);
    cudaMemsetAsync(s_ctr, 0, sizeof(unsigned), 0);

    fused_kernel<<<TOTAL_BLOCKS, 96>>>(in, wl, bl, w1, b1, w2, b2, w3, b3, out);
}